// round 9
// baseline (speedup 1.0000x reference)
#include <cuda_runtime.h>

// Shapes: x0 [8,256,256,64] f32, x1 [8,128,128,64] f32.
// Output = concat(out0 [8,256,256,64], repl [8,128,128,64], out3 [8,256,256,64]).
//
// R6 structure (best isolated: 68.4us): two adjacent pooled blocks per thread,
// float4 accesses, 10 front-batched loads.
// This round: streaming (.cs evict-first) STORES only — the 302MB of output is
// never re-read; keep it from thrashing L2 against the read stream. Loads stay
// default (R2 showed .cs loads regress).

#define NTHREADS  1048576     // 8*128*64*16
#define BLOCK     128
#define REPL_F4   8388608     // 33,554,432 / 4
#define OUT3_F4   10485760    // + 8,388,608 / 4

__device__ __forceinline__ void lane(
    float v0, float v1, float v2, float v3, float p,
    float& o0, float& o1, float& o2, float& o3,
    float& rep,
    float& q0, float& q1, float& q2, float& q3)
{
    // Value-only descending sort (5-comparator network).
    float a0 = fmaxf(v0, v1), a1 = fminf(v0, v1);
    float a2 = fmaxf(v2, v3), a3 = fminf(v2, v3);
    float s0 = fmaxf(a0, a2), m0 = fminf(a0, a2);
    float s3t = fminf(a1, a3), m1 = fmaxf(a1, a3);
    float s1 = fmaxf(m1, m0), s2 = fminf(m1, m0);

    // Optimal-average scan: avg_j = (cumsum_j + p)/(j+2); first max wins.
    float cs   = s0 + p;
    float best = cs / 2.0f;
    int   k    = 0;
    cs += s1; { float t = cs / 3.0f; if (t > best) { best = t; k = 1; } }
    cs += s2; { float t = cs / 4.0f; if (t > best) { best = t; k = 2; } }
    cs += s3t;{ float t = cs / 5.0f; if (t > best) { best = t; k = 3; } }
    rep = best;

    float frac = (float)(k + 1) / (float)(k + 2);

    // Stable descending rank: rank_l = #{m: v_m > v_l} + #{m<l: v_m == v_l}
    int r0 = (int)(v1 > v0)  + (int)(v2 > v0)  + (int)(v3 > v0);
    int r1 = (int)(v0 >= v1) + (int)(v2 > v1)  + (int)(v3 > v1);
    int r2 = (int)(v0 >= v2) + (int)(v1 >= v2) + (int)(v3 > v2);
    int r3 = (int)(v0 >= v3) + (int)(v1 >= v3) + (int)(v2 >= v3);

    bool m0b = r0 <= k, m1b = r1 <= k, m2b = r2 <= k, m3b = r3 <= k;
    o0 = m0b ? best : v0;  q0 = m0b ? frac : 1.0f;
    o1 = m1b ? best : v1;  q1 = m1b ? frac : 1.0f;
    o2 = m2b ? best : v2;  q2 = m2b ? frac : 1.0f;
    o3 = m3b ? best : v3;  q3 = m3b ? frac : 1.0f;
}

// Process one 2x2 block (4 channels via float4 SIMD-in-register).
__device__ __forceinline__ void do_block(
    float4 A, float4 Bv, float4 Cv, float4 D, float4 P,
    float4& OA, float4& OB, float4& OC, float4& OD,
    float4& R, float4& TA, float4& TB, float4& TC, float4& TD)
{
    lane(A.x, Bv.x, Cv.x, D.x, P.x, OA.x, OB.x, OC.x, OD.x, R.x, TA.x, TB.x, TC.x, TD.x);
    lane(A.y, Bv.y, Cv.y, D.y, P.y, OA.y, OB.y, OC.y, OD.y, R.y, TA.y, TB.y, TC.y, TD.y);
    lane(A.z, Bv.z, Cv.z, D.z, P.z, OA.z, OB.z, OC.z, OD.z, R.z, TA.z, TB.z, TC.z, TD.z);
    lane(A.w, Bv.w, Cv.w, D.w, P.w, OA.w, OB.w, OC.w, OD.w, R.w, TA.w, TB.w, TC.w, TD.w);
}

__global__ void unpool_ls_kernel(const float4* __restrict__ x0,
                                 const float4* __restrict__ x1,
                                 float4* __restrict__ out)
{
    int idx = blockIdx.x * BLOCK + threadIdx.x;   // covers exactly NTHREADS

    // idx decomposition: [b:3][h:7][wp:6][c4:4]  (wp = pooled-w pair)
    int c4 = idx & 15;
    int t  = idx >> 4;
    int wp = t & 63;
    t >>= 6;
    int h  = t & 127;
    int b  = t >> 7;

    // x0 float4 base at (2h, 4wp): row stride = 4096 float4.
    int base  = (b * 256 + 2 * h) * 4096 + wp * 64 + c4;
    // x1 float4 index at (h, 2wp):
    int pidx  = (b * 128 + h) * 2048 + wp * 32 + c4;

    // Front-batched independent loads (10 x LDG.128, default cache policy).
    float4 A0 = x0[base];            // blk0 (2h,   4wp)
    float4 B0 = x0[base + 16];       // blk0 (2h,   4wp+1)
    float4 A1 = x0[base + 32];       // blk1 (2h,   4wp+2)
    float4 B1 = x0[base + 48];       // blk1 (2h,   4wp+3)
    float4 C0 = x0[base + 4096];     // blk0 (2h+1, 4wp)
    float4 D0 = x0[base + 4112];     // blk0 (2h+1, 4wp+1)
    float4 C1 = x0[base + 4128];     // blk1 (2h+1, 4wp+2)
    float4 D1 = x0[base + 4144];     // blk1 (2h+1, 4wp+3)
    float4 P0 = x1[pidx];            // pooled (h, 2wp)
    float4 P1 = x1[pidx + 16];       // pooled (h, 2wp+1)

    float4 OA, OB, OC, OD, R, TA, TB, TC, TD;

    // ---- block 0 ----
    do_block(A0, B0, C0, D0, P0, OA, OB, OC, OD, R, TA, TB, TC, TD);
    __stcs(out + base,            OA);
    __stcs(out + base + 16,       OB);
    __stcs(out + base + 4096,     OC);
    __stcs(out + base + 4112,     OD);
    __stcs(out + REPL_F4 + pidx,  R);
    __stcs(out + OUT3_F4 + base,        TA);
    __stcs(out + OUT3_F4 + base + 16,   TB);
    __stcs(out + OUT3_F4 + base + 4096, TC);
    __stcs(out + OUT3_F4 + base + 4112, TD);

    // ---- block 1 ----
    do_block(A1, B1, C1, D1, P1, OA, OB, OC, OD, R, TA, TB, TC, TD);
    __stcs(out + base + 32,       OA);
    __stcs(out + base + 48,       OB);
    __stcs(out + base + 4128,     OC);
    __stcs(out + base + 4144,     OD);
    __stcs(out + REPL_F4 + pidx + 16, R);
    __stcs(out + OUT3_F4 + base + 32,   TA);
    __stcs(out + OUT3_F4 + base + 48,   TB);
    __stcs(out + OUT3_F4 + base + 4128, TC);
    __stcs(out + OUT3_F4 + base + 4144, TD);
}

extern "C" void kernel_launch(void* const* d_in, const int* in_sizes, int n_in,
                              void* d_out, int out_size)
{
    (void)in_sizes; (void)n_in; (void)out_size;
    const float4* x0 = (const float4*)d_in[0];
    const float4* x1 = (const float4*)d_in[1];
    float4* out = (float4*)d_out;

    unpool_ls_kernel<<<NTHREADS / BLOCK, BLOCK>>>(x0, x1, out);
}

// round 11
// speedup vs baseline: 1.0087x; 1.0087x over previous
#include <cuda_runtime.h>

// Shapes: x0 [8,256,256,64] f32, x1 [8,128,128,64] f32.
// Output = concat(out0 [8,256,256,64], repl [8,128,128,64], out3 [8,256,256,64]).
//
// Structure (best isolated so far): two adjacent pooled blocks per thread,
// float4 accesses, 10 front-batched independent LDG.128, 18 STG.128.
// This round: __ldcg loads (bypass L1 — all data is one-touch, L1 gives zero
// hits and only adds queue latency) + __stcs stores (evict-first, neutral in
// R9 but keeps L2 clean for the read stream). No launch bounds / no reg cap:
// the earlier "hint regression" (R2/R5) was spill traffic from the 40-reg cap
// (L1% spiked to 58.7 there), not the hints themselves.

#define NTHREADS  1048576     // 8*128*64*16
#define BLOCK     128
#define REPL_F4   8388608     // 33,554,432 / 4
#define OUT3_F4   10485760    // + 8,388,608 / 4

__device__ __forceinline__ void lane(
    float v0, float v1, float v2, float v3, float p,
    float& o0, float& o1, float& o2, float& o3,
    float& rep,
    float& q0, float& q1, float& q2, float& q3)
{
    // Value-only descending sort (5-comparator network).
    float a0 = fmaxf(v0, v1), a1 = fminf(v0, v1);
    float a2 = fmaxf(v2, v3), a3 = fminf(v2, v3);
    float s0 = fmaxf(a0, a2), m0 = fminf(a0, a2);
    float s3t = fminf(a1, a3), m1 = fmaxf(a1, a3);
    float s1 = fmaxf(m1, m0), s2 = fminf(m1, m0);

    // Optimal-average scan: avg_j = (cumsum_j + p)/(j+2); first max wins.
    float cs   = s0 + p;
    float best = cs / 2.0f;
    int   k    = 0;
    cs += s1; { float t = cs / 3.0f; if (t > best) { best = t; k = 1; } }
    cs += s2; { float t = cs / 4.0f; if (t > best) { best = t; k = 2; } }
    cs += s3t;{ float t = cs / 5.0f; if (t > best) { best = t; k = 3; } }
    rep = best;

    float frac = (float)(k + 1) / (float)(k + 2);

    // Stable descending rank: rank_l = #{m: v_m > v_l} + #{m<l: v_m == v_l}
    int r0 = (int)(v1 > v0)  + (int)(v2 > v0)  + (int)(v3 > v0);
    int r1 = (int)(v0 >= v1) + (int)(v2 > v1)  + (int)(v3 > v1);
    int r2 = (int)(v0 >= v2) + (int)(v1 >= v2) + (int)(v3 > v2);
    int r3 = (int)(v0 >= v3) + (int)(v1 >= v3) + (int)(v2 >= v3);

    bool m0b = r0 <= k, m1b = r1 <= k, m2b = r2 <= k, m3b = r3 <= k;
    o0 = m0b ? best : v0;  q0 = m0b ? frac : 1.0f;
    o1 = m1b ? best : v1;  q1 = m1b ? frac : 1.0f;
    o2 = m2b ? best : v2;  q2 = m2b ? frac : 1.0f;
    o3 = m3b ? best : v3;  q3 = m3b ? frac : 1.0f;
}

// Process one 2x2 block (4 channels via float4 SIMD-in-register).
__device__ __forceinline__ void do_block(
    float4 A, float4 Bv, float4 Cv, float4 D, float4 P,
    float4& OA, float4& OB, float4& OC, float4& OD,
    float4& R, float4& TA, float4& TB, float4& TC, float4& TD)
{
    lane(A.x, Bv.x, Cv.x, D.x, P.x, OA.x, OB.x, OC.x, OD.x, R.x, TA.x, TB.x, TC.x, TD.x);
    lane(A.y, Bv.y, Cv.y, D.y, P.y, OA.y, OB.y, OC.y, OD.y, R.y, TA.y, TB.y, TC.y, TD.y);
    lane(A.z, Bv.z, Cv.z, D.z, P.z, OA.z, OB.z, OC.z, OD.z, R.z, TA.z, TB.z, TC.z, TD.z);
    lane(A.w, Bv.w, Cv.w, D.w, P.w, OA.w, OB.w, OC.w, OD.w, R.w, TA.w, TB.w, TC.w, TD.w);
}

__global__ void unpool_ls_kernel(const float4* __restrict__ x0,
                                 const float4* __restrict__ x1,
                                 float4* __restrict__ out)
{
    int idx = blockIdx.x * BLOCK + threadIdx.x;   // covers exactly NTHREADS

    // idx decomposition: [b:3][h:7][wp:6][c4:4]  (wp = pooled-w pair)
    int c4 = idx & 15;
    int t  = idx >> 4;
    int wp = t & 63;
    t >>= 6;
    int h  = t & 127;
    int b  = t >> 7;

    // x0 float4 base at (2h, 4wp): row stride = 4096 float4.
    int base  = (b * 256 + 2 * h) * 4096 + wp * 64 + c4;
    // x1 float4 index at (h, 2wp):
    int pidx  = (b * 128 + h) * 2048 + wp * 32 + c4;

    // Front-batched independent loads (10 x LDG.128.CG — bypass L1).
    float4 A0 = __ldcg(x0 + base);            // blk0 (2h,   4wp)
    float4 B0 = __ldcg(x0 + base + 16);       // blk0 (2h,   4wp+1)
    float4 A1 = __ldcg(x0 + base + 32);       // blk1 (2h,   4wp+2)
    float4 B1 = __ldcg(x0 + base + 48);       // blk1 (2h,   4wp+3)
    float4 C0 = __ldcg(x0 + base + 4096);     // blk0 (2h+1, 4wp)
    float4 D0 = __ldcg(x0 + base + 4112);     // blk0 (2h+1, 4wp+1)
    float4 C1 = __ldcg(x0 + base + 4128);     // blk1 (2h+1, 4wp+2)
    float4 D1 = __ldcg(x0 + base + 4144);     // blk1 (2h+1, 4wp+3)
    float4 P0 = __ldcg(x1 + pidx);            // pooled (h, 2wp)
    float4 P1 = __ldcg(x1 + pidx + 16);       // pooled (h, 2wp+1)

    float4 OA, OB, OC, OD, R, TA, TB, TC, TD;

    // ---- block 0 ----
    do_block(A0, B0, C0, D0, P0, OA, OB, OC, OD, R, TA, TB, TC, TD);
    __stcs(out + base,            OA);
    __stcs(out + base + 16,       OB);
    __stcs(out + base + 4096,     OC);
    __stcs(out + base + 4112,     OD);
    __stcs(out + REPL_F4 + pidx,  R);
    __stcs(out + OUT3_F4 + base,        TA);
    __stcs(out + OUT3_F4 + base + 16,   TB);
    __stcs(out + OUT3_F4 + base + 4096, TC);
    __stcs(out + OUT3_F4 + base + 4112, TD);

    // ---- block 1 ----
    do_block(A1, B1, C1, D1, P1, OA, OB, OC, OD, R, TA, TB, TC, TD);
    __stcs(out + base + 32,       OA);
    __stcs(out + base + 48,       OB);
    __stcs(out + base + 4128,     OC);
    __stcs(out + base + 4144,     OD);
    __stcs(out + REPL_F4 + pidx + 16, R);
    __stcs(out + OUT3_F4 + base + 32,   TA);
    __stcs(out + OUT3_F4 + base + 48,   TB);
    __stcs(out + OUT3_F4 + base + 4128, TC);
    __stcs(out + OUT3_F4 + base + 4144, TD);
}

extern "C" void kernel_launch(void* const* d_in, const int* in_sizes, int n_in,
                              void* d_out, int out_size)
{
    (void)in_sizes; (void)n_in; (void)out_size;
    const float4* x0 = (const float4*)d_in[0];
    const float4* x1 = (const float4*)d_in[1];
    float4* out = (float4*)d_out;

    unpool_ls_kernel<<<NTHREADS / BLOCK, BLOCK>>>(x0, x1, out);
}